// round 2
// baseline (speedup 1.0000x reference)
#include <cuda_runtime.h>

// MultiPartLoss: YOLO-style loss over (N, 49, 30) preds/targets, fp32.
// Layout per cell (30 floats): [20 class probs][2 conf][2 boxes x (x,y,w,h)]
// Single-kernel design: stream both tensors once (cp.async -> smem tile,
// thread-per-cell compute), per-block partials, last-block-done final
// reduction in double precision. No second kernel launch.

#define C_CLS 20
#define F 30                    // floats per cell
#define TPB 64                  // threads per block == cells per tile (64 | M)
#define TILE_FLOATS (TPB * F)   // 1920 floats = 7680 B per tensor
#define TILE_V4     (TILE_FLOATS / 4)  // 480 float4 per tensor
#define BLK_PER_SM 14
#define NBLK (148 * BLK_PER_SM) // 2072
#define MAX_PART 4096
#define NOOBJ 0.5f

__device__ float g_partials[MAX_PART];
__device__ unsigned int g_count = 0;

__device__ __forceinline__ void cp_async16(void* smem_dst, const void* gmem_src) {
    unsigned int saddr = (unsigned int)__cvta_generic_to_shared(smem_dst);
    asm volatile("cp.async.cg.shared.global [%0], [%1], 16;\n"
                 :: "r"(saddr), "l"(gmem_src));
}

__global__ __launch_bounds__(TPB) void mploss_fused(
    const float* __restrict__ preds,
    const float* __restrict__ targets,
    int M,          // total cells
    float invN)
{
    __shared__ float sp[TILE_FLOATS];
    __shared__ float st[TILE_FLOATS];
    __shared__ bool  s_is_last;

    float acc = 0.0f;
    const int numTiles = (M + TPB - 1) / TPB;

    for (int tile = blockIdx.x; tile < numTiles; tile += gridDim.x) {
        const long long base = (long long)tile * TILE_FLOATS;
        const long long remaining = (long long)M * F - base;

        if (remaining >= TILE_FLOATS) {
            const float4* p4 = (const float4*)(preds + base);
            const float4* t4 = (const float4*)(targets + base);
            float4* sp4 = (float4*)sp;
            float4* st4 = (float4*)st;
            #pragma unroll
            for (int i = threadIdx.x; i < TILE_V4; i += TPB) {
                cp_async16(sp4 + i, p4 + i);
                cp_async16(st4 + i, t4 + i);
            }
            asm volatile("cp.async.commit_group;\n" ::: "memory");
            asm volatile("cp.async.wait_group 0;\n" ::: "memory");
        } else {
            for (int i = threadIdx.x; i < (int)remaining; i += TPB) {
                sp[i] = preds[base + i];
                st[i] = targets[base + i];
            }
        }
        __syncthreads();

        const int cell = tile * TPB + threadIdx.x;
        if (cell < M) {
            const float* p = sp + threadIdx.x * F;
            const float* t = st + threadIdx.x * F;

            // no-object confidence term (both boxes, always)
            float dc0 = p[20] - t[20];
            float dc1 = p[21] - t[21];
            float l = NOOBJ * (dc0 * dc0 + dc1 * dc1);

            // obj flag: class targets are one-hot * obj -> sum is exactly 0 or 1
            float s = 0.0f;
            #pragma unroll
            for (int c = 0; c < C_CLS; c++) s += t[c];
            const bool obj = (s == 1.0f);

            if (obj) {
                float iou[2];
                #pragma unroll
                for (int b = 0; b < 2; b++) {
                    const int o = 22 + 4 * b;
                    float px = p[o], py = p[o + 1], pw = p[o + 2], ph = p[o + 3];
                    float tx = t[o], ty = t[o + 1], tw = t[o + 2], th = t[o + 3];
                    float xA = fmaxf(px - pw * 0.5f, tx - tw * 0.5f);
                    float xB = fminf(px + pw * 0.5f, tx + tw * 0.5f);
                    float yA = fmaxf(py - ph * 0.5f, ty - th * 0.5f);
                    float yB = fminf(py + ph * 0.5f, ty + th * 0.5f);
                    float inter = fmaxf(0.0f, xB - xA + 1.0f) *
                                  fmaxf(0.0f, yB - yA + 1.0f);
                    float uni = pw * ph + tw * th - inter;
                    iou[b] = inter / uni;
                }
                // jnp.argmax: first max wins -> top=1 only if strictly greater
                const int top = (iou[1] > iou[0]) ? 1 : 0;
                const int o = 22 + 4 * top;

                float dct = p[20 + top] - t[20 + top];
                l += (1.0f - NOOBJ) * dct * dct;

                float cls = 0.0f;
                #pragma unroll
                for (int c = 0; c < C_CLS; c++) {
                    float d = p[c] - t[c];
                    cls += d * d;
                }
                l += cls;

                float dx = p[o] - t[o];
                float dy = p[o + 1] - t[o + 1];
                l += dx * dx + dy * dy;

                float dw = sqrtf(p[o + 2]) - sqrtf(t[o + 2]);
                float dh = sqrtf(p[o + 3]) - sqrtf(t[o + 3]);
                l += dw * dw + dh * dh;
            }
            acc += l;
        }
        __syncthreads();
    }

    // intra-warp reduce (fixed order -> deterministic)
    #pragma unroll
    for (int off = 16; off > 0; off >>= 1)
        acc += __shfl_down_sync(0xFFFFFFFFu, acc, off);

    __shared__ float warp_sums[TPB / 32];
    const int lane = threadIdx.x & 31;
    const int wid  = threadIdx.x >> 5;
    if (lane == 0) warp_sums[wid] = acc;
    __syncthreads();

    if (threadIdx.x == 0) {
        float bsum = 0.0f;
        #pragma unroll
        for (int w = 0; w < TPB / 32; w++) bsum += warp_sums[w];
        g_partials[blockIdx.x] = bsum;
        __threadfence();
        unsigned int prev = atomicAdd(&g_count, 1u);
        s_is_last = (prev == gridDim.x - 1);
    }
    __syncthreads();
    return;
}

// Second pass handled inside mploss_fused's last block below via a separate
// epilogue kernel? No — keep single kernel; see epilogue in the same kernel.

__global__ __launch_bounds__(TPB) void mploss_fused2(
    const float* __restrict__ preds,
    const float* __restrict__ targets,
    int M, float invN, float* __restrict__ out)
{
    __shared__ float sp[TILE_FLOATS];
    __shared__ float st[TILE_FLOATS];
    __shared__ bool  s_is_last;
    __shared__ double dsum[TPB];

    float acc = 0.0f;
    const int numTiles = (M + TPB - 1) / TPB;

    for (int tile = blockIdx.x; tile < numTiles; tile += gridDim.x) {
        const long long base = (long long)tile * TILE_FLOATS;
        const long long remaining = (long long)M * F - base;

        if (remaining >= TILE_FLOATS) {
            const float4* p4 = (const float4*)(preds + base);
            const float4* t4 = (const float4*)(targets + base);
            float4* sp4 = (float4*)sp;
            float4* st4 = (float4*)st;
            #pragma unroll
            for (int i = threadIdx.x; i < TILE_V4; i += TPB) {
                cp_async16(sp4 + i, p4 + i);
                cp_async16(st4 + i, t4 + i);
            }
            asm volatile("cp.async.commit_group;\n" ::: "memory");
            asm volatile("cp.async.wait_group 0;\n" ::: "memory");
        } else {
            for (int i = threadIdx.x; i < (int)remaining; i += TPB) {
                sp[i] = preds[base + i];
                st[i] = targets[base + i];
            }
        }
        __syncthreads();

        const int cell = tile * TPB + threadIdx.x;
        if (cell < M) {
            const float* p = sp + threadIdx.x * F;
            const float* t = st + threadIdx.x * F;

            float dc0 = p[20] - t[20];
            float dc1 = p[21] - t[21];
            float l = NOOBJ * (dc0 * dc0 + dc1 * dc1);

            float s = 0.0f;
            #pragma unroll
            for (int c = 0; c < C_CLS; c++) s += t[c];
            const bool obj = (s == 1.0f);

            if (obj) {
                float iou[2];
                #pragma unroll
                for (int b = 0; b < 2; b++) {
                    const int o = 22 + 4 * b;
                    float px = p[o], py = p[o + 1], pw = p[o + 2], ph = p[o + 3];
                    float tx = t[o], ty = t[o + 1], tw = t[o + 2], th = t[o + 3];
                    float xA = fmaxf(px - pw * 0.5f, tx - tw * 0.5f);
                    float xB = fminf(px + pw * 0.5f, tx + tw * 0.5f);
                    float yA = fmaxf(py - ph * 0.5f, ty - th * 0.5f);
                    float yB = fminf(py + ph * 0.5f, ty + th * 0.5f);
                    float inter = fmaxf(0.0f, xB - xA + 1.0f) *
                                  fmaxf(0.0f, yB - yA + 1.0f);
                    float uni = pw * ph + tw * th - inter;
                    iou[b] = inter / uni;
                }
                const int top = (iou[1] > iou[0]) ? 1 : 0;
                const int o = 22 + 4 * top;

                float dct = p[20 + top] - t[20 + top];
                l += (1.0f - NOOBJ) * dct * dct;

                float cls = 0.0f;
                #pragma unroll
                for (int c = 0; c < C_CLS; c++) {
                    float d = p[c] - t[c];
                    cls += d * d;
                }
                l += cls;

                float dx = p[o] - t[o];
                float dy = p[o + 1] - t[o + 1];
                l += dx * dx + dy * dy;

                float dw = sqrtf(p[o + 2]) - sqrtf(t[o + 2]);
                float dh = sqrtf(p[o + 3]) - sqrtf(t[o + 3]);
                l += dw * dw + dh * dh;
            }
            acc += l;
        }
        __syncthreads();
    }

    // intra-warp reduce (fixed order -> deterministic)
    #pragma unroll
    for (int off = 16; off > 0; off >>= 1)
        acc += __shfl_down_sync(0xFFFFFFFFu, acc, off);

    __shared__ float warp_sums[TPB / 32];
    const int lane = threadIdx.x & 31;
    const int wid  = threadIdx.x >> 5;
    if (lane == 0) warp_sums[wid] = acc;
    __syncthreads();

    if (threadIdx.x == 0) {
        float bsum = 0.0f;
        #pragma unroll
        for (int w = 0; w < TPB / 32; w++) bsum += warp_sums[w];
        g_partials[blockIdx.x] = bsum;
        __threadfence();
        unsigned int prev = atomicAdd(&g_count, 1u);
        s_is_last = (prev == gridDim.x - 1);
    }
    __syncthreads();

    // Last finished block performs the deterministic final reduction.
    if (s_is_last) {
        double s = 0.0;
        for (int i = threadIdx.x; i < (int)gridDim.x; i += TPB)
            s += (double)g_partials[i];
        dsum[threadIdx.x] = s;
        __syncthreads();
        #pragma unroll
        for (int stride = TPB / 2; stride > 0; stride >>= 1) {
            if (threadIdx.x < stride) dsum[threadIdx.x] += dsum[threadIdx.x + stride];
            __syncthreads();
        }
        if (threadIdx.x == 0) {
            out[0] = (float)(dsum[0] * (double)invN);
            g_count = 0;   // reset for next graph replay
        }
    }
}

extern "C" void kernel_launch(void* const* d_in, const int* in_sizes, int n_in,
                              void* d_out, int out_size)
{
    const float* preds   = (const float*)d_in[0];
    const float* targets = (const float*)d_in[1];
    float* out = (float*)d_out;

    const int M = in_sizes[0] / F;        // total grid cells
    const int N = M / 49;                 // batch size (S*S = 49)
    const float invN = 1.0f / (float)N;

    int nblk = NBLK;
    int numTiles = (M + TPB - 1) / TPB;
    if (nblk > numTiles) nblk = numTiles;
    if (nblk > MAX_PART) nblk = MAX_PART;

    mploss_fused2<<<nblk, TPB>>>(preds, targets, M, invN, out);
}

// round 3
// speedup vs baseline: 1.1174x; 1.1174x over previous
#include <cuda_runtime.h>

// MultiPartLoss: YOLO-style loss over (N, 49, 30) preds/targets, fp32.
// Layout per cell (30 floats): [20 class][2 conf][2 boxes x (x,y,w,h)]
// Single persistent kernel: 2-stage cp.async double-buffered pipeline
// (gmem -> smem), thread-per-cell compute, per-block partials, fused
// last-block final reduction in double precision.

#define C_CLS 20
#define F 30
#define TPB 128                       // cells per tile; 128 | 1605632
#define STAGE_FLOATS (TPB * F)        // 3840 floats per tensor per stage
#define STAGE_V4 (STAGE_FLOATS / 4)   // 960 float4 per tensor
#define STAGE_TOTAL (2 * STAGE_FLOATS)      // both tensors, one stage
#define SMEM_FLOATS (2 * STAGE_TOTAL)       // two stages
#define SMEM_BYTES (SMEM_FLOATS * 4)        // 61440 B dynamic smem
#define BLK_PER_SM 3
#define NBLK (148 * BLK_PER_SM)       // 444 persistent blocks
#define MAX_PART 4096
#define NOOBJ 0.5f

__device__ float g_partials[MAX_PART];
__device__ unsigned int g_count = 0;

__device__ __forceinline__ void cp_async16(void* smem_dst, const void* gmem_src) {
    unsigned int saddr = (unsigned int)__cvta_generic_to_shared(smem_dst);
    asm volatile("cp.async.cg.shared.global [%0], [%1], 16;\n"
                 :: "r"(saddr), "l"(gmem_src));
}

extern __shared__ float smem[];   // [stage][tensor][STAGE_FLOATS]

__device__ __forceinline__ void load_stage(int stage, int tile,
                                           const float* __restrict__ preds,
                                           const float* __restrict__ targets,
                                           int M)
{
    float* sp = smem + stage * STAGE_TOTAL;
    float* st = sp + STAGE_FLOATS;
    const long long base = (long long)tile * STAGE_FLOATS;
    const long long remaining = (long long)M * F - base;

    if (remaining >= STAGE_FLOATS) {
        const float4* p4 = (const float4*)(preds + base);
        const float4* t4 = (const float4*)(targets + base);
        float4* sp4 = (float4*)sp;
        float4* st4 = (float4*)st;
        for (int i = threadIdx.x; i < STAGE_V4; i += TPB) {
            cp_async16(sp4 + i, p4 + i);
            cp_async16(st4 + i, t4 + i);
        }
    } else {
        // tail (never hit for the bench shape, kept for generality)
        for (int i = threadIdx.x; i < (int)remaining; i += TPB) {
            sp[i] = preds[base + i];
            st[i] = targets[base + i];
        }
    }
}

__device__ __forceinline__ float compute_cell(int stage, int tile, int M)
{
    const int cell = tile * TPB + threadIdx.x;
    if (cell >= M) return 0.0f;

    const float* p = smem + stage * STAGE_TOTAL + threadIdx.x * F;
    const float* t = p + STAGE_FLOATS;

    // no-object confidence term (both boxes, always)
    float dc0 = p[20] - t[20];
    float dc1 = p[21] - t[21];
    float l = NOOBJ * (dc0 * dc0 + dc1 * dc1);

    // obj flag: class targets are one-hot * obj -> sum is exactly 0 or 1
    float s = 0.0f;
    #pragma unroll
    for (int c = 0; c < C_CLS; c++) s += t[c];
    const bool obj = (s == 1.0f);

    if (obj) {
        float iou[2];
        #pragma unroll
        for (int b = 0; b < 2; b++) {
            const int o = 22 + 4 * b;
            float px = p[o], py = p[o + 1], pw = p[o + 2], ph = p[o + 3];
            float tx = t[o], ty = t[o + 1], tw = t[o + 2], th = t[o + 3];
            float xA = fmaxf(px - pw * 0.5f, tx - tw * 0.5f);
            float xB = fminf(px + pw * 0.5f, tx + tw * 0.5f);
            float yA = fmaxf(py - ph * 0.5f, ty - th * 0.5f);
            float yB = fminf(py + ph * 0.5f, ty + th * 0.5f);
            float inter = fmaxf(0.0f, xB - xA + 1.0f) *
                          fmaxf(0.0f, yB - yA + 1.0f);
            float uni = pw * ph + tw * th - inter;
            iou[b] = inter / uni;
        }
        // jnp.argmax: first max wins -> top=1 only if strictly greater
        const int top = (iou[1] > iou[0]) ? 1 : 0;
        const int o = 22 + 4 * top;

        float dct = p[20 + top] - t[20 + top];
        l += (1.0f - NOOBJ) * dct * dct;

        float cls = 0.0f;
        #pragma unroll
        for (int c = 0; c < C_CLS; c++) {
            float d = p[c] - t[c];
            cls += d * d;
        }
        l += cls;

        float dx = p[o] - t[o];
        float dy = p[o + 1] - t[o + 1];
        l += dx * dx + dy * dy;

        float dw = sqrtf(p[o + 2]) - sqrtf(t[o + 2]);
        float dh = sqrtf(p[o + 3]) - sqrtf(t[o + 3]);
        l += dw * dw + dh * dh;
    }
    return l;
}

__global__ __launch_bounds__(TPB) void mploss_pipe(
    const float* __restrict__ preds,
    const float* __restrict__ targets,
    int M, float invN, float* __restrict__ out)
{
    __shared__ bool s_is_last;
    __shared__ float warp_sums[TPB / 32];
    __shared__ double dsum[TPB];

    const int numTiles = (M + TPB - 1) / TPB;
    float acc = 0.0f;

    // Prologue: prefetch first tile into stage 0.
    int tile = blockIdx.x;
    if (tile < numTiles)
        load_stage(0, tile, preds, targets, M);
    asm volatile("cp.async.commit_group;\n" ::: "memory");

    int it = 0;
    for (; tile < numTiles; tile += gridDim.x, it ^= 1) {
        const int nextTile = tile + gridDim.x;
        if (nextTile < numTiles)
            load_stage(it ^ 1, nextTile, preds, targets, M);
        asm volatile("cp.async.commit_group;\n" ::: "memory");

        // Pending: [current tile group, next tile group]. Wait current.
        asm volatile("cp.async.wait_group 1;\n" ::: "memory");
        __syncthreads();

        acc += compute_cell(it, tile, M);
        __syncthreads();   // buffer `it` safe to overwrite next iteration
    }

    // Deterministic per-block reduction (fixed order).
    #pragma unroll
    for (int off = 16; off > 0; off >>= 1)
        acc += __shfl_down_sync(0xFFFFFFFFu, acc, off);

    const int lane = threadIdx.x & 31;
    const int wid  = threadIdx.x >> 5;
    if (lane == 0) warp_sums[wid] = acc;
    __syncthreads();

    if (threadIdx.x == 0) {
        float bsum = 0.0f;
        #pragma unroll
        for (int w = 0; w < TPB / 32; w++) bsum += warp_sums[w];
        g_partials[blockIdx.x] = bsum;
        __threadfence();
        unsigned int prev = atomicAdd(&g_count, 1u);
        s_is_last = (prev == gridDim.x - 1);
    }
    __syncthreads();

    // Last finished block: deterministic final reduction in double.
    if (s_is_last) {
        double s = 0.0;
        for (int i = threadIdx.x; i < (int)gridDim.x; i += TPB)
            s += (double)g_partials[i];
        dsum[threadIdx.x] = s;
        __syncthreads();
        #pragma unroll
        for (int stride = TPB / 2; stride > 0; stride >>= 1) {
            if (threadIdx.x < stride) dsum[threadIdx.x] += dsum[threadIdx.x + stride];
            __syncthreads();
        }
        if (threadIdx.x == 0) {
            out[0] = (float)(dsum[0] * (double)invN);
            g_count = 0;   // reset for next graph replay
        }
    }
}

extern "C" void kernel_launch(void* const* d_in, const int* in_sizes, int n_in,
                              void* d_out, int out_size)
{
    const float* preds   = (const float*)d_in[0];
    const float* targets = (const float*)d_in[1];
    float* out = (float*)d_out;

    const int M = in_sizes[0] / F;        // total grid cells
    const int N = M / 49;                 // batch size (S*S = 49)
    const float invN = 1.0f / (float)N;

    cudaFuncSetAttribute(mploss_pipe,
                         cudaFuncAttributeMaxDynamicSharedMemorySize,
                         SMEM_BYTES);

    int numTiles = (M + TPB - 1) / TPB;
    int nblk = NBLK;
    if (nblk > numTiles) nblk = numTiles;
    if (nblk > MAX_PART) nblk = MAX_PART;

    mploss_pipe<<<nblk, TPB, SMEM_BYTES>>>(preds, targets, M, invN, out);
}

// round 4
// speedup vs baseline: 1.1360x; 1.0166x over previous
#include <cuda_runtime.h>

// MultiPartLoss: YOLO-style loss over (N, 49, 30) preds/targets, fp32.
// Layout per cell (30 floats): [20 class][2 conf][2 boxes x (x,y,w,h)]
// Persistent kernel, 2-stage cp.async double-buffered pipeline, compute
// reads smem exclusively via conflict-free float2 (LDS.64), per-block
// partials, fused last-block double-precision finalize.

#define C_CLS 20
#define F 30
#define F2 (F / 2)                    // 15 float2 per cell
#define TPB 128                       // cells per tile; 128 | 1605632
#define STAGE_FLOATS (TPB * F)        // 3840 floats per tensor per stage
#define STAGE_V4 (STAGE_FLOATS / 4)   // 960 float4 per tensor
#define STAGE_TOTAL (2 * STAGE_FLOATS)
#define SMEM_FLOATS (2 * STAGE_TOTAL)
#define SMEM_BYTES (SMEM_FLOATS * 4)  // 61440 B dynamic smem
#define BLK_PER_SM 3
#define NBLK (148 * BLK_PER_SM)       // 444 persistent blocks
#define MAX_PART 4096
#define NOOBJ 0.5f

__device__ float g_partials[MAX_PART];
__device__ unsigned int g_count = 0;

__device__ __forceinline__ void cp_async16(void* smem_dst, const void* gmem_src) {
    unsigned int saddr = (unsigned int)__cvta_generic_to_shared(smem_dst);
    asm volatile("cp.async.cg.shared.global [%0], [%1], 16;\n"
                 :: "r"(saddr), "l"(gmem_src));
}

extern __shared__ float smem[];   // [stage][tensor][STAGE_FLOATS]

__device__ __forceinline__ void load_stage(int stage, int tile,
                                           const float* __restrict__ preds,
                                           const float* __restrict__ targets,
                                           int M)
{
    float* sp = smem + stage * STAGE_TOTAL;
    float* st = sp + STAGE_FLOATS;
    const long long base = (long long)tile * STAGE_FLOATS;
    const long long remaining = (long long)M * F - base;

    if (remaining >= STAGE_FLOATS) {
        const float4* p4 = (const float4*)(preds + base);
        const float4* t4 = (const float4*)(targets + base);
        float4* sp4 = (float4*)sp;
        float4* st4 = (float4*)st;
        #pragma unroll
        for (int i = threadIdx.x; i < STAGE_V4; i += TPB) {
            cp_async16(sp4 + i, p4 + i);
            cp_async16(st4 + i, t4 + i);
        }
    } else {
        for (int i = threadIdx.x; i < (int)remaining; i += TPB) {
            sp[i] = preds[base + i];
            st[i] = targets[base + i];
        }
    }
}

__device__ __forceinline__ float compute_cell(int stage, int tile, int M)
{
    const int cell = tile * TPB + threadIdx.x;
    if (cell >= M) return 0.0f;

    // Cell base: 30 floats (120 B, 8-byte aligned) -> 15 aligned float2.
    // Stride 30 words with LDS.64 is bank-conflict-free.
    const float2* p2 = (const float2*)(smem + stage * STAGE_TOTAL) + threadIdx.x * F2;
    const float2* t2 = p2 + (STAGE_FLOATS / 2);

    // ---- confidences (floats 20,21 = float2 index 10) ----
    float2 pc = p2[10];
    float2 tc = t2[10];
    float dc0 = pc.x - tc.x;
    float dc1 = pc.y - tc.y;
    float l = NOOBJ * (dc0 * dc0 + dc1 * dc1);

    // ---- obj flag: class targets are one-hot * obj -> sum is 0 or 1 ----
    float s = 0.0f;
    float2 tcl[10];
    #pragma unroll
    for (int c = 0; c < 10; c++) {
        tcl[c] = t2[c];
        s += tcl[c].x + tcl[c].y;
    }
    const bool obj = (s == 1.0f);

    if (obj) {
        // boxes: idx 11=(x0,y0) 12=(w0,h0) 13=(x1,y1) 14=(w1,h1)
        float2 pxy0 = p2[11], pwh0 = p2[12], pxy1 = p2[13], pwh1 = p2[14];
        float2 txy0 = t2[11], twh0 = t2[12], txy1 = t2[13], twh1 = t2[14];

        float iou[2];
        #pragma unroll
        for (int b = 0; b < 2; b++) {
            float px = b ? pxy1.x : pxy0.x, py = b ? pxy1.y : pxy0.y;
            float pw = b ? pwh1.x : pwh0.x, ph = b ? pwh1.y : pwh0.y;
            float tx = b ? txy1.x : txy0.x, ty = b ? txy1.y : txy0.y;
            float tw = b ? twh1.x : twh0.x, th = b ? twh1.y : twh0.y;
            float xA = fmaxf(px - pw * 0.5f, tx - tw * 0.5f);
            float xB = fminf(px + pw * 0.5f, tx + tw * 0.5f);
            float yA = fmaxf(py - ph * 0.5f, ty - th * 0.5f);
            float yB = fminf(py + ph * 0.5f, ty + th * 0.5f);
            float inter = fmaxf(0.0f, xB - xA + 1.0f) *
                          fmaxf(0.0f, yB - yA + 1.0f);
            float uni = pw * ph + tw * th - inter;
            iou[b] = inter / uni;
        }
        // jnp.argmax: first max wins -> top=1 only if strictly greater
        const bool top1 = (iou[1] > iou[0]);

        // responsible-box confidence
        float pct = top1 ? pc.y : pc.x;
        float tct = top1 ? tc.y : tc.x;
        float dct = pct - tct;
        l += (1.0f - NOOBJ) * dct * dct;

        // class probabilities
        float cls = 0.0f;
        #pragma unroll
        for (int c = 0; c < 10; c++) {
            float2 pcl = p2[c];
            float dx = pcl.x - tcl[c].x;
            float dy = pcl.y - tcl[c].y;
            cls += dx * dx + dy * dy;
        }
        l += cls;

        // xy of responsible box
        float2 pxy = top1 ? pxy1 : pxy0;
        float2 txy = top1 ? txy1 : txy0;
        float dx = pxy.x - txy.x;
        float dy = pxy.y - txy.y;
        l += dx * dx + dy * dy;

        // sqrt(wh) of responsible box
        float2 pwh = top1 ? pwh1 : pwh0;
        float2 twh = top1 ? twh1 : twh0;
        float dw = sqrtf(pwh.x) - sqrtf(twh.x);
        float dh = sqrtf(pwh.y) - sqrtf(twh.y);
        l += dw * dw + dh * dh;
    }
    return l;
}

__global__ __launch_bounds__(TPB) void mploss_pipe(
    const float* __restrict__ preds,
    const float* __restrict__ targets,
    int M, float invN, float* __restrict__ out)
{
    __shared__ bool s_is_last;
    __shared__ float warp_sums[TPB / 32];
    __shared__ double dsum[TPB];

    const int numTiles = (M + TPB - 1) / TPB;
    float acc = 0.0f;

    // Prologue: prefetch first tile into stage 0.
    int tile = blockIdx.x;
    if (tile < numTiles)
        load_stage(0, tile, preds, targets, M);
    asm volatile("cp.async.commit_group;\n" ::: "memory");

    int it = 0;
    for (; tile < numTiles; tile += gridDim.x, it ^= 1) {
        const int nextTile = tile + gridDim.x;
        if (nextTile < numTiles)
            load_stage(it ^ 1, nextTile, preds, targets, M);
        asm volatile("cp.async.commit_group;\n" ::: "memory");

        // Pending groups: [current, next]. Wait for current only.
        asm volatile("cp.async.wait_group 1;\n" ::: "memory");
        __syncthreads();

        acc += compute_cell(it, tile, M);
        __syncthreads();   // buffer `it` safe to overwrite next iteration
    }

    // Deterministic per-block reduction (fixed order).
    #pragma unroll
    for (int off = 16; off > 0; off >>= 1)
        acc += __shfl_down_sync(0xFFFFFFFFu, acc, off);

    const int lane = threadIdx.x & 31;
    const int wid  = threadIdx.x >> 5;
    if (lane == 0) warp_sums[wid] = acc;
    __syncthreads();

    if (threadIdx.x == 0) {
        float bsum = 0.0f;
        #pragma unroll
        for (int w = 0; w < TPB / 32; w++) bsum += warp_sums[w];
        g_partials[blockIdx.x] = bsum;
        __threadfence();
        unsigned int prev = atomicAdd(&g_count, 1u);
        s_is_last = (prev == gridDim.x - 1);
    }
    __syncthreads();

    // Last finished block: deterministic final reduction in double.
    if (s_is_last) {
        double s = 0.0;
        for (int i = threadIdx.x; i < (int)gridDim.x; i += TPB)
            s += (double)g_partials[i];
        dsum[threadIdx.x] = s;
        __syncthreads();
        #pragma unroll
        for (int stride = TPB / 2; stride > 0; stride >>= 1) {
            if (threadIdx.x < stride) dsum[threadIdx.x] += dsum[threadIdx.x + stride];
            __syncthreads();
        }
        if (threadIdx.x == 0) {
            out[0] = (float)(dsum[0] * (double)invN);
            g_count = 0;   // reset for next graph replay
        }
    }
}

extern "C" void kernel_launch(void* const* d_in, const int* in_sizes, int n_in,
                              void* d_out, int out_size)
{
    const float* preds   = (const float*)d_in[0];
    const float* targets = (const float*)d_in[1];
    float* out = (float*)d_out;

    const int M = in_sizes[0] / F;        // total grid cells
    const int N = M / 49;                 // batch size (S*S = 49)
    const float invN = 1.0f / (float)N;

    cudaFuncSetAttribute(mploss_pipe,
                         cudaFuncAttributeMaxDynamicSharedMemorySize,
                         SMEM_BYTES);

    int numTiles = (M + TPB - 1) / TPB;
    int nblk = NBLK;
    if (nblk > numTiles) nblk = numTiles;
    if (nblk > MAX_PART) nblk = MAX_PART;

    mploss_pipe<<<nblk, TPB, SMEM_BYTES>>>(preds, targets, M, invN, out);
}

// round 5
// speedup vs baseline: 1.1404x; 1.0039x over previous
#include <cuda_runtime.h>

// MultiPartLoss: YOLO-style loss over (N, 49, 30) preds/targets, fp32.
// Persistent kernel. TMA bulk copies (cp.async.bulk.shared::cta) feed a
// 3-stage smem pipeline via mbarrier complete_tx; compute reads smem with
// conflict-free float2; per-block partials; fused last-block finalize.

#define C_CLS 20
#define F 30
#define F2 (F / 2)
#define TPB 128                        // cells per tile; 128 | 1605632
#define STAGES 3
#define STAGE_FLOATS (TPB * F)         // 3840 floats per tensor per stage
#define STAGE_BYTES_T (STAGE_FLOATS * 4)     // 15360 B per tensor
#define STAGE_TOTAL (2 * STAGE_FLOATS)       // both tensors: 7680 floats
#define STAGE_BYTES (STAGE_TOTAL * 4)        // 30720 B
#define SMEM_BYTES (STAGES * STAGE_BYTES)    // 92160 B dynamic smem
#define BLK_PER_SM 2
#define NBLK (148 * BLK_PER_SM)        // 296 persistent blocks
#define MAX_PART 4096
#define NOOBJ 0.5f

__device__ float g_partials[MAX_PART];
__device__ unsigned int g_count = 0;

extern __shared__ float smem[];        // [stage][tensor][STAGE_FLOATS]

__device__ __forceinline__ unsigned int smem_u32(const void* p) {
    return (unsigned int)__cvta_generic_to_shared(p);
}

__device__ __forceinline__ void bulk_copy(void* smem_dst, const void* gmem_src,
                                          unsigned int bytes, unsigned int mbar) {
    asm volatile(
        "cp.async.bulk.shared::cta.global.mbarrier::complete_tx::bytes "
        "[%0], [%1], %2, [%3];"
        :: "r"(smem_u32(smem_dst)), "l"(gmem_src), "r"(bytes), "r"(mbar)
        : "memory");
}

__device__ __forceinline__ void mbar_wait(unsigned int mbar, unsigned int parity) {
    unsigned int done;
    asm volatile(
        "{\n\t.reg .pred p;\n\t"
        "mbarrier.try_wait.parity.acquire.cta.shared::cta.b64 p, [%1], %2;\n\t"
        "selp.b32 %0, 1, 0, p;\n\t}"
        : "=r"(done) : "r"(mbar), "r"(parity) : "memory");
    if (!done) {
        asm volatile(
            "{\n\t.reg .pred P1;\n\t"
            "WAIT_LOOP_%=:\n\t"
            "mbarrier.try_wait.parity.acquire.cta.shared::cta.b64 P1, [%0], %1, 0x989680;\n\t"
            "@P1 bra.uni WAIT_DONE_%=;\n\t"
            "bra.uni WAIT_LOOP_%=;\n\t"
            "WAIT_DONE_%=:\n\t}"
            :: "r"(mbar), "r"(parity) : "memory");
    }
}

// Elected-thread producer: expect full stage bytes, then two bulk copies.
__device__ __forceinline__ void produce(int s, int tile,
                                        const float* __restrict__ preds,
                                        const float* __restrict__ targets,
                                        unsigned int mbar) {
    if (threadIdx.x == 0) {
        float* sp = smem + s * STAGE_TOTAL;
        const long long base = (long long)tile * STAGE_FLOATS;
        asm volatile(
            "mbarrier.arrive.expect_tx.shared::cta.b64 _, [%0], %1;"
            :: "r"(mbar), "r"((unsigned int)STAGE_BYTES) : "memory");
        bulk_copy(sp, preds + base, STAGE_BYTES_T, mbar);
        bulk_copy(sp + STAGE_FLOATS, targets + base, STAGE_BYTES_T, mbar);
    }
}

__device__ __forceinline__ float compute_cell(int stage, int tile, int M)
{
    const int cell = tile * TPB + threadIdx.x;
    if (cell >= M) return 0.0f;

    // 30 floats per cell (120 B, 8B-aligned) -> 15 aligned float2 loads.
    const float2* p2 = (const float2*)(smem + stage * STAGE_TOTAL) + threadIdx.x * F2;
    const float2* t2 = p2 + (STAGE_FLOATS / 2);

    float2 pc = p2[10];
    float2 tc = t2[10];
    float dc0 = pc.x - tc.x;
    float dc1 = pc.y - tc.y;
    float l = NOOBJ * (dc0 * dc0 + dc1 * dc1);

    // obj: class targets are one-hot * obj -> sum is exactly 0 or 1
    float s = 0.0f;
    float2 tcl[10];
    #pragma unroll
    for (int c = 0; c < 10; c++) {
        tcl[c] = t2[c];
        s += tcl[c].x + tcl[c].y;
    }
    const bool obj = (s == 1.0f);

    if (obj) {
        float2 pxy0 = p2[11], pwh0 = p2[12], pxy1 = p2[13], pwh1 = p2[14];
        float2 txy0 = t2[11], twh0 = t2[12], txy1 = t2[13], twh1 = t2[14];

        float iou[2];
        #pragma unroll
        for (int b = 0; b < 2; b++) {
            float px = b ? pxy1.x : pxy0.x, py = b ? pxy1.y : pxy0.y;
            float pw = b ? pwh1.x : pwh0.x, ph = b ? pwh1.y : pwh0.y;
            float tx = b ? txy1.x : txy0.x, ty = b ? txy1.y : txy0.y;
            float tw = b ? twh1.x : twh0.x, th = b ? twh1.y : twh0.y;
            float xA = fmaxf(px - pw * 0.5f, tx - tw * 0.5f);
            float xB = fminf(px + pw * 0.5f, tx + tw * 0.5f);
            float yA = fmaxf(py - ph * 0.5f, ty - th * 0.5f);
            float yB = fminf(py + ph * 0.5f, ty + th * 0.5f);
            float inter = fmaxf(0.0f, xB - xA + 1.0f) *
                          fmaxf(0.0f, yB - yA + 1.0f);
            float uni = pw * ph + tw * th - inter;
            iou[b] = inter / uni;
        }
        const bool top1 = (iou[1] > iou[0]);   // argmax: first max wins

        float dct = (top1 ? pc.y : pc.x) - (top1 ? tc.y : tc.x);
        l += (1.0f - NOOBJ) * dct * dct;

        float cls = 0.0f;
        #pragma unroll
        for (int c = 0; c < 10; c++) {
            float2 pcl = p2[c];
            float dx = pcl.x - tcl[c].x;
            float dy = pcl.y - tcl[c].y;
            cls += dx * dx + dy * dy;
        }
        l += cls;

        float2 pxy = top1 ? pxy1 : pxy0;
        float2 txy = top1 ? txy1 : txy0;
        float dx = pxy.x - txy.x;
        float dy = pxy.y - txy.y;
        l += dx * dx + dy * dy;

        float2 pwh = top1 ? pwh1 : pwh0;
        float2 twh = top1 ? twh1 : twh0;
        float dw = sqrtf(pwh.x) - sqrtf(twh.x);
        float dh = sqrtf(pwh.y) - sqrtf(twh.y);
        l += dw * dw + dh * dh;
    }
    return l;
}

__global__ __launch_bounds__(TPB) void mploss_tma(
    const float* __restrict__ preds,
    const float* __restrict__ targets,
    int M, float invN, float* __restrict__ out)
{
    __shared__ __align__(8) unsigned long long mbar_storage[STAGES];
    __shared__ bool s_is_last;
    __shared__ float warp_sums[TPB / 32];
    __shared__ double dsum[TPB];

    const long long totalFloats = (long long)M * F;
    const int numTiles = (M + TPB - 1) / TPB;

    // Init mbarriers (arrive count 1 = the producer's expect_tx arrival).
    if (threadIdx.x == 0) {
        #pragma unroll
        for (int s = 0; s < STAGES; s++) {
            unsigned int a = smem_u32(&mbar_storage[s]);
            asm volatile("mbarrier.init.shared::cta.b64 [%0], 1;" :: "r"(a) : "memory");
        }
        asm volatile("fence.proxy.async.shared::cta;" ::: "memory");
    }
    __syncthreads();

    unsigned int mbar[STAGES];
    #pragma unroll
    for (int s = 0; s < STAGES; s++) mbar[s] = smem_u32(&mbar_storage[s]);

    // Prologue: prefetch up to STAGES tiles.
    #pragma unroll
    for (int k = 0; k < STAGES; k++) {
        int tk = blockIdx.x + k * gridDim.x;
        if (tk < numTiles &&
            (long long)(tk + 1) * STAGE_FLOATS <= totalFloats)
            produce(k, tk, preds, targets, mbar[k]);
    }

    float acc = 0.0f;
    unsigned int phases = 0;   // one parity bit per stage
    int s = 0;

    for (int tile = blockIdx.x; tile < numTiles; tile += gridDim.x) {
        const bool full = ((long long)(tile + 1) * STAGE_FLOATS <= totalFloats);

        if (full) {
            mbar_wait(mbar[s], (phases >> s) & 1u);
            phases ^= (1u << s);
        } else {
            // tail tile (not hit for the bench shape): cooperative loads
            float* sp = smem + s * STAGE_TOTAL;
            float* st = sp + STAGE_FLOATS;
            const long long base = (long long)tile * STAGE_FLOATS;
            const int remaining = (int)(totalFloats - base);
            for (int i = threadIdx.x; i < remaining; i += TPB) {
                sp[i] = preds[base + i];
                st[i] = targets[base + i];
            }
            __syncthreads();
        }

        acc += compute_cell(s, tile, M);
        __syncthreads();   // all threads done reading stage s

        const int next = tile + STAGES * gridDim.x;
        if (next < numTiles &&
            (long long)(next + 1) * STAGE_FLOATS <= totalFloats)
            produce(s, next, preds, targets, mbar[s]);

        s = (s + 1 == STAGES) ? 0 : s + 1;
    }

    // Deterministic per-block reduction.
    #pragma unroll
    for (int off = 16; off > 0; off >>= 1)
        acc += __shfl_down_sync(0xFFFFFFFFu, acc, off);

    const int lane = threadIdx.x & 31;
    const int wid  = threadIdx.x >> 5;
    if (lane == 0) warp_sums[wid] = acc;
    __syncthreads();

    if (threadIdx.x == 0) {
        float bsum = 0.0f;
        #pragma unroll
        for (int w = 0; w < TPB / 32; w++) bsum += warp_sums[w];
        g_partials[blockIdx.x] = bsum;
        __threadfence();
        unsigned int prev = atomicAdd(&g_count, 1u);
        s_is_last = (prev == gridDim.x - 1);
    }
    __syncthreads();

    // Last finished block: deterministic double-precision finalize.
    if (s_is_last) {
        double d = 0.0;
        for (int i = threadIdx.x; i < (int)gridDim.x; i += TPB)
            d += (double)g_partials[i];
        dsum[threadIdx.x] = d;
        __syncthreads();
        #pragma unroll
        for (int stride = TPB / 2; stride > 0; stride >>= 1) {
            if (threadIdx.x < stride) dsum[threadIdx.x] += dsum[threadIdx.x + stride];
            __syncthreads();
        }
        if (threadIdx.x == 0) {
            out[0] = (float)(dsum[0] * (double)invN);
            g_count = 0;   // reset for next graph replay
        }
    }
}

extern "C" void kernel_launch(void* const* d_in, const int* in_sizes, int n_in,
                              void* d_out, int out_size)
{
    const float* preds   = (const float*)d_in[0];
    const float* targets = (const float*)d_in[1];
    float* out = (float*)d_out;

    const int M = in_sizes[0] / F;
    const int N = M / 49;
    const float invN = 1.0f / (float)N;

    cudaFuncSetAttribute(mploss_tma,
                         cudaFuncAttributeMaxDynamicSharedMemorySize,
                         SMEM_BYTES);

    int numTiles = (M + TPB - 1) / TPB;
    int nblk = NBLK;
    if (nblk > numTiles) nblk = numTiles;
    if (nblk > MAX_PART) nblk = MAX_PART;

    mploss_tma<<<nblk, TPB, SMEM_BYTES>>>(preds, targets, M, invN, out);
}

// round 6
// speedup vs baseline: 1.1511x; 1.0094x over previous
#include <cuda_runtime.h>

// MultiPartLoss: YOLO-style loss over (N, 49, 30) preds/targets, fp32.
// Persistent kernel. TMA bulk copies (cp.async.bulk.shared::cta) feed a
// 3-stage smem pipeline via mbarrier complete_tx; compute reads smem with
// conflict-free float2; per-block partials; fused last-block finalize.
// Grid chosen so every block processes EXACTLY the same number of tiles
// (512 blocks x 49 tiles for the bench shape) -> zero tail imbalance.

#define C_CLS 20
#define F 30
#define F2 (F / 2)
#define TPB 64                         // cells per tile
#define STAGES 3
#define STAGE_FLOATS (TPB * F)         // 1920 floats per tensor per stage
#define STAGE_BYTES_T (STAGE_FLOATS * 4)     // 7680 B per tensor
#define STAGE_TOTAL (2 * STAGE_FLOATS)       // both tensors: 3840 floats
#define STAGE_BYTES (STAGE_TOTAL * 4)        // 15360 B
#define SMEM_BYTES (STAGES * STAGE_BYTES)    // 46080 B dynamic smem
#define NBLK_BAL 512                   // 512 | 25088 tiles -> 49 tiles/block
#define NBLK_MAX 592                   // 148 SMs * 4 resident blocks
#define MAX_PART 4096
#define NOOBJ 0.5f

__device__ float g_partials[MAX_PART];
__device__ unsigned int g_count = 0;

extern __shared__ float smem[];        // [stage][tensor][STAGE_FLOATS]

__device__ __forceinline__ unsigned int smem_u32(const void* p) {
    return (unsigned int)__cvta_generic_to_shared(p);
}

__device__ __forceinline__ void bulk_copy(void* smem_dst, const void* gmem_src,
                                          unsigned int bytes, unsigned int mbar) {
    asm volatile(
        "cp.async.bulk.shared::cta.global.mbarrier::complete_tx::bytes "
        "[%0], [%1], %2, [%3];"
        :: "r"(smem_u32(smem_dst)), "l"(gmem_src), "r"(bytes), "r"(mbar)
        : "memory");
}

__device__ __forceinline__ void mbar_wait(unsigned int mbar, unsigned int parity) {
    unsigned int done;
    asm volatile(
        "{\n\t.reg .pred p;\n\t"
        "mbarrier.try_wait.parity.acquire.cta.shared::cta.b64 p, [%1], %2;\n\t"
        "selp.b32 %0, 1, 0, p;\n\t}"
        : "=r"(done) : "r"(mbar), "r"(parity) : "memory");
    if (!done) {
        asm volatile(
            "{\n\t.reg .pred P1;\n\t"
            "WAIT_LOOP_%=:\n\t"
            "mbarrier.try_wait.parity.acquire.cta.shared::cta.b64 P1, [%0], %1, 0x989680;\n\t"
            "@P1 bra.uni WAIT_DONE_%=;\n\t"
            "bra.uni WAIT_LOOP_%=;\n\t"
            "WAIT_DONE_%=:\n\t}"
            :: "r"(mbar), "r"(parity) : "memory");
    }
}

__device__ __forceinline__ void produce(int s, int tile,
                                        const float* __restrict__ preds,
                                        const float* __restrict__ targets,
                                        unsigned int mbar) {
    if (threadIdx.x == 0) {
        float* sp = smem + s * STAGE_TOTAL;
        const long long base = (long long)tile * STAGE_FLOATS;
        asm volatile(
            "mbarrier.arrive.expect_tx.shared::cta.b64 _, [%0], %1;"
            :: "r"(mbar), "r"((unsigned int)STAGE_BYTES) : "memory");
        bulk_copy(sp, preds + base, STAGE_BYTES_T, mbar);
        bulk_copy(sp + STAGE_FLOATS, targets + base, STAGE_BYTES_T, mbar);
    }
}

__device__ __forceinline__ float compute_cell(int stage, int tile, int M)
{
    const int cell = tile * TPB + threadIdx.x;
    if (cell >= M) return 0.0f;

    // 30 floats per cell (120 B, 8B-aligned) -> 15 aligned float2 loads.
    const float2* p2 = (const float2*)(smem + stage * STAGE_TOTAL) + threadIdx.x * F2;
    const float2* t2 = p2 + (STAGE_FLOATS / 2);

    float2 pc = p2[10];
    float2 tc = t2[10];
    float dc0 = pc.x - tc.x;
    float dc1 = pc.y - tc.y;
    float l = NOOBJ * (dc0 * dc0 + dc1 * dc1);

    // obj: class targets are one-hot * obj -> sum is exactly 0 or 1
    float s = 0.0f;
    float2 tcl[10];
    #pragma unroll
    for (int c = 0; c < 10; c++) {
        tcl[c] = t2[c];
        s += tcl[c].x + tcl[c].y;
    }
    const bool obj = (s == 1.0f);

    if (obj) {
        float2 pxy0 = p2[11], pwh0 = p2[12], pxy1 = p2[13], pwh1 = p2[14];
        float2 txy0 = t2[11], twh0 = t2[12], txy1 = t2[13], twh1 = t2[14];

        float iou[2];
        #pragma unroll
        for (int b = 0; b < 2; b++) {
            float px = b ? pxy1.x : pxy0.x, py = b ? pxy1.y : pxy0.y;
            float pw = b ? pwh1.x : pwh0.x, ph = b ? pwh1.y : pwh0.y;
            float tx = b ? txy1.x : txy0.x, ty = b ? txy1.y : txy0.y;
            float tw = b ? twh1.x : twh0.x, th = b ? twh1.y : twh0.y;
            float xA = fmaxf(px - pw * 0.5f, tx - tw * 0.5f);
            float xB = fminf(px + pw * 0.5f, tx + tw * 0.5f);
            float yA = fmaxf(py - ph * 0.5f, ty - th * 0.5f);
            float yB = fminf(py + ph * 0.5f, ty + th * 0.5f);
            float inter = fmaxf(0.0f, xB - xA + 1.0f) *
                          fmaxf(0.0f, yB - yA + 1.0f);
            float uni = pw * ph + tw * th - inter;
            iou[b] = inter / uni;
        }
        const bool top1 = (iou[1] > iou[0]);   // argmax: first max wins

        float dct = (top1 ? pc.y : pc.x) - (top1 ? tc.y : tc.x);
        l += (1.0f - NOOBJ) * dct * dct;

        float cls = 0.0f;
        #pragma unroll
        for (int c = 0; c < 10; c++) {
            float2 pcl = p2[c];
            float dx = pcl.x - tcl[c].x;
            float dy = pcl.y - tcl[c].y;
            cls += dx * dx + dy * dy;
        }
        l += cls;

        float2 pxy = top1 ? pxy1 : pxy0;
        float2 txy = top1 ? txy1 : txy0;
        float dx = pxy.x - txy.x;
        float dy = pxy.y - txy.y;
        l += dx * dx + dy * dy;

        float2 pwh = top1 ? pwh1 : pwh0;
        float2 twh = top1 ? twh1 : twh0;
        float dw = sqrtf(pwh.x) - sqrtf(twh.x);
        float dh = sqrtf(pwh.y) - sqrtf(twh.y);
        l += dw * dw + dh * dh;
    }
    return l;
}

__global__ __launch_bounds__(TPB) void mploss_tma(
    const float* __restrict__ preds,
    const float* __restrict__ targets,
    int M, float invN, float* __restrict__ out)
{
    __shared__ __align__(8) unsigned long long mbar_storage[STAGES];
    __shared__ bool s_is_last;
    __shared__ float warp_sums[TPB / 32];
    __shared__ double dsum[TPB];

    const long long totalFloats = (long long)M * F;
    const int numTiles = (M + TPB - 1) / TPB;

    if (threadIdx.x == 0) {
        #pragma unroll
        for (int s = 0; s < STAGES; s++) {
            unsigned int a = smem_u32(&mbar_storage[s]);
            asm volatile("mbarrier.init.shared::cta.b64 [%0], 1;" :: "r"(a) : "memory");
        }
        asm volatile("fence.proxy.async.shared::cta;" ::: "memory");
    }
    __syncthreads();

    unsigned int mbar[STAGES];
    #pragma unroll
    for (int s = 0; s < STAGES; s++) mbar[s] = smem_u32(&mbar_storage[s]);

    // Prologue: prefetch up to STAGES tiles.
    #pragma unroll
    for (int k = 0; k < STAGES; k++) {
        int tk = blockIdx.x + k * gridDim.x;
        if (tk < numTiles &&
            (long long)(tk + 1) * STAGE_FLOATS <= totalFloats)
            produce(k, tk, preds, targets, mbar[k]);
    }

    float acc = 0.0f;
    unsigned int phases = 0;
    int s = 0;

    for (int tile = blockIdx.x; tile < numTiles; tile += gridDim.x) {
        const bool full = ((long long)(tile + 1) * STAGE_FLOATS <= totalFloats);

        if (full) {
            mbar_wait(mbar[s], (phases >> s) & 1u);
            phases ^= (1u << s);
        } else {
            // tail tile (not hit for the bench shape): cooperative loads
            float* sp = smem + s * STAGE_TOTAL;
            float* st = sp + STAGE_FLOATS;
            const long long base = (long long)tile * STAGE_FLOATS;
            const int remaining = (int)(totalFloats - base);
            for (int i = threadIdx.x; i < remaining; i += TPB) {
                sp[i] = preds[base + i];
                st[i] = targets[base + i];
            }
            __syncthreads();
        }

        acc += compute_cell(s, tile, M);
        __syncthreads();   // all threads done reading stage s

        const int next = tile + STAGES * gridDim.x;
        if (next < numTiles &&
            (long long)(next + 1) * STAGE_FLOATS <= totalFloats)
            produce(s, next, preds, targets, mbar[s]);

        s = (s + 1 == STAGES) ? 0 : s + 1;
    }

    // Deterministic per-block reduction.
    #pragma unroll
    for (int off = 16; off > 0; off >>= 1)
        acc += __shfl_down_sync(0xFFFFFFFFu, acc, off);

    const int lane = threadIdx.x & 31;
    const int wid  = threadIdx.x >> 5;
    if (lane == 0) warp_sums[wid] = acc;
    __syncthreads();

    if (threadIdx.x == 0) {
        float bsum = 0.0f;
        #pragma unroll
        for (int w = 0; w < TPB / 32; w++) bsum += warp_sums[w];
        g_partials[blockIdx.x] = bsum;
        __threadfence();
        unsigned int prev = atomicAdd(&g_count, 1u);
        s_is_last = (prev == gridDim.x - 1);
    }
    __syncthreads();

    // Last finished block: deterministic double-precision finalize.
    if (s_is_last) {
        double d = 0.0;
        for (int i = threadIdx.x; i < (int)gridDim.x; i += TPB)
            d += (double)g_partials[i];
        dsum[threadIdx.x] = d;
        __syncthreads();
        #pragma unroll
        for (int stride = TPB / 2; stride > 0; stride >>= 1) {
            if (threadIdx.x < stride) dsum[threadIdx.x] += dsum[threadIdx.x + stride];
            __syncthreads();
        }
        if (threadIdx.x == 0) {
            out[0] = (float)(dsum[0] * (double)invN);
            g_count = 0;   // reset for next graph replay
        }
    }
}

extern "C" void kernel_launch(void* const* d_in, const int* in_sizes, int n_in,
                              void* d_out, int out_size)
{
    const float* preds   = (const float*)d_in[0];
    const float* targets = (const float*)d_in[1];
    float* out = (float*)d_out;

    const int M = in_sizes[0] / F;
    const int N = M / 49;
    const float invN = 1.0f / (float)N;

    cudaFuncSetAttribute(mploss_tma,
                         cudaFuncAttributeMaxDynamicSharedMemorySize,
                         SMEM_BYTES);

    const int numTiles = (M + TPB - 1) / TPB;

    // Prefer a grid that divides numTiles exactly (perfect balance).
    int nblk;
    if (numTiles % NBLK_BAL == 0)      nblk = NBLK_BAL;
    else if (numTiles % 448 == 0)      nblk = 448;
    else if (numTiles % 392 == 0)      nblk = 392;
    else if (numTiles % 256 == 0)      nblk = 256;
    else                               nblk = NBLK_MAX;
    if (nblk > numTiles) nblk = numTiles;
    if (nblk > MAX_PART) nblk = MAX_PART;

    mploss_tma<<<nblk, TPB, SMEM_BYTES>>>(preds, targets, M, invN, out);
}